// round 15
// baseline (speedup 1.0000x reference)
#include <cuda_runtime.h>
#include <math.h>
#include <float.h>

#define B_   8
#define N_   4096
#define M_   1024
#define K_   32
#define CIN_ 64
#define CT_  64
#define C1_  64
#define C2_  128
#define G_   8

// ---------------- device scratch (no allocations allowed) ----------------
__device__ int    g_nidx[B_ * M_ * K_];
__device__ float  g_fT[B_ * N_ * CIN_];          // features transposed [b][n][c]
__device__ float  g_tT[B_ * N_ * CT_];           // temb transposed     [b][n][c]
__device__ float  g_pn[B_ * N_];                 // per-point squared norms
__device__ float  g_z1[B_ * C1_ * M_ * K_];      // [b][c][m][k]
__device__ float  g_z2[B_ * C2_ * M_ * K_];      // [b][c][m][k]
__device__ double g_p1[B_ * G_ * 512 * 2];
__device__ double g_p2[B_ * G_ * 256 * 2];
__device__ float  g_ms1[B_ * G_ * 2];
__device__ float  g_ms2[B_ * G_ * 2];

// ---------------- packed f32x2 helpers (bit-exact per-lane IEEE) ----------
typedef unsigned long long ull;
__device__ __forceinline__ ull pk2(float lo, float hi) {
    ull r; asm("mov.b64 %0, {%1, %2};" : "=l"(r) : "f"(lo), "f"(hi)); return r;
}
__device__ __forceinline__ void upk2(ull v, float& lo, float& hi) {
    asm("mov.b64 {%0, %1}, %2;" : "=f"(lo), "=f"(hi) : "l"(v));
}
__device__ __forceinline__ ull add2(ull a, ull b) {
    ull r; asm("add.rn.f32x2 %0, %1, %2;" : "=l"(r) : "l"(a), "l"(b)); return r;
}
__device__ __forceinline__ ull mul2(ull a, ull b) {
    ull r; asm("mul.rn.f32x2 %0, %1, %2;" : "=l"(r) : "l"(a), "l"(b)); return r;
}
__device__ __forceinline__ ull fma2(ull a, ull b, ull c) {
    ull r; asm("fma.rn.f32x2 %0, %1, %2, %3;" : "=l"(r) : "l"(a), "l"(b), "l"(c)); return r;
}

// ---------------------------------------------------------------------
// Transpose one tensor: [b][64][4096] -> [b][4096][64]
// ---------------------------------------------------------------------
template <int WHICH>
__global__ void tr_kernel(const float* __restrict__ src) {
    __shared__ float tile[32][33];
    float* dst = WHICH ? g_tT : g_fT;
    const int b = blockIdx.z;
    const int n0 = blockIdx.x * 32, c0 = blockIdx.y * 32;
    tile[threadIdx.y][threadIdx.x] =
        src[((size_t)b * 64 + c0 + threadIdx.y) * N_ + n0 + threadIdx.x];
    __syncthreads();
    dst[((size_t)b * N_ + n0 + threadIdx.y) * 64 + c0 + threadIdx.x] =
        tile[threadIdx.x][threadIdx.y];
}

// ---------------------------------------------------------------------
// Point squared norms (same fma chain knn used -> bit-identical d)
// ---------------------------------------------------------------------
__global__ void pn_kernel(const float* __restrict__ coords) {
    const int i = blockIdx.x * 256 + threadIdx.x;
    const int b = i >> 12, n = i & (N_ - 1);
    float x = coords[(b * 3 + 0) * N_ + n];
    float y = coords[(b * 3 + 1) * N_ + n];
    float z = coords[(b * 3 + 2) * N_ + n];
    g_pn[i] = fmaf(z, z, fmaf(y, y, __fmul_rn(x, x)));
}

// ---------------------------------------------------------------------
// FPS v3: one block/batch, 256 threads, 16 pts/thread in registers
// (packed f32x2 updates). Batch coords mirrored in smem so the winner
// publishes only its point index; everyone broadcasts coords from smem.
// Arithmetic chain identical to prior rounds (bit-exact selections):
//   d = fma(dz,dz, fma(dy,dy, mul(dx,dx))),  dx = p + (-f)  ==  p - f.
// Tie-breaking: strict > scan keeps lowest j; lane/warp order == n order.
// ---------------------------------------------------------------------
__global__ __launch_bounds__(256) void fps_kernel(const float* __restrict__ coords,
                                                  float* __restrict__ centers) {
    const int b = blockIdx.x;
    const float* cx = coords + (b * 3 + 0) * N_;
    const float* cy = coords + (b * 3 + 1) * N_;
    const float* cz = coords + (b * 3 + 2) * N_;
    const int t = threadIdx.x, lane = t & 31, wid = t >> 5;
    const int n0 = t * 16;

    __shared__ float sCx[N_], sCy[N_], sCz[N_];   // 48 KB
    __shared__ unsigned swk[2][8];
    __shared__ int      swn[2][8];

    // mirror coords into smem (coalesced)
    for (int i = t; i < N_; i += 256) {
        sCx[i] = cx[i]; sCy[i] = cy[i]; sCz[i] = cz[i];
    }

    // registers: 16 points as 8 packed pairs per dim
    ull pxp[8], pyp[8], pzp[8];
#pragma unroll
    for (int q = 0; q < 4; q++) {
        float4 vx = *(const float4*)(cx + n0 + 4 * q);
        float4 vy = *(const float4*)(cy + n0 + 4 * q);
        float4 vz = *(const float4*)(cz + n0 + 4 * q);
        pxp[2 * q] = pk2(vx.x, vx.y); pxp[2 * q + 1] = pk2(vx.z, vx.w);
        pyp[2 * q] = pk2(vy.x, vy.y); pyp[2 * q + 1] = pk2(vy.z, vy.w);
        pzp[2 * q] = pk2(vz.x, vz.y); pzp[2 * q + 1] = pk2(vz.z, vz.w);
    }

    float fx = __ldg(cx), fy = __ldg(cy), fz = __ldg(cz);
    if (t == 0) {
        centers[(b * 3 + 0) * M_] = fx;
        centers[(b * 3 + 1) * M_] = fy;
        centers[(b * 3 + 2) * M_] = fz;
    }

    float dist[16];
    {
        ull nfx = pk2(-fx, -fx), nfy = pk2(-fy, -fy), nfz = pk2(-fz, -fz);
#pragma unroll
        for (int j = 0; j < 8; j++) {
            ull dx = add2(pxp[j], nfx);
            ull dy = add2(pyp[j], nfy);
            ull dz = add2(pzp[j], nfz);
            ull sq = fma2(dz, dz, fma2(dy, dy, mul2(dx, dx)));
            upk2(sq, dist[2 * j], dist[2 * j + 1]);
        }
    }
    __syncthreads();   // smem mirror ready
    int p = 0;

    for (int s = 1; s < M_; s++) {
        // local argmax over 16 (strict > keeps lowest index)
        float bd = dist[0];
        int   bj = 0;
#pragma unroll
        for (int j = 1; j < 16; j++)
            if (dist[j] > bd) { bd = dist[j]; bj = j; }

        unsigned key  = __float_as_uint(bd);      // dist >= 0: bits monotone
        unsigned wmax = __reduce_max_sync(0xffffffffu, key);
        unsigned msk  = __ballot_sync(0xffffffffu, key == wmax);
        if (lane == __ffs(msk) - 1) {
            swk[p][wid] = wmax;
            swn[p][wid] = n0 + bj;
        }
        __syncthreads();

        // every warp redundantly reduces the 8 warp entries
        unsigned k2  = (lane < 8) ? swk[p][lane] : 0u;
        unsigned m2  = __reduce_max_sync(0xffffffffu, k2);
        unsigned mk2 = __ballot_sync(0xffffffffu, k2 == m2);
        int nf = swn[p][__ffs(mk2) - 1];
        fx = sCx[nf]; fy = sCy[nf]; fz = sCz[nf];   // broadcast LDS
        if (t == 0) {
            centers[(b * 3 + 0) * M_ + s] = fx;
            centers[(b * 3 + 1) * M_ + s] = fy;
            centers[(b * 3 + 2) * M_ + s] = fz;
        }
        ull nfx = pk2(-fx, -fx), nfy = pk2(-fy, -fy), nfz = pk2(-fz, -fz);
#pragma unroll
        for (int j = 0; j < 8; j++) {
            ull dx = add2(pxp[j], nfx);
            ull dy = add2(pyp[j], nfy);
            ull dz = add2(pzp[j], nfz);
            ull sq = fma2(dz, dz, fma2(dy, dy, mul2(dx, dx)));
            float d0, d1; upk2(sq, d0, d1);
            dist[2 * j]     = fminf(dist[2 * j],     d0);
            dist[2 * j + 1] = fminf(dist[2 * j + 1], d1);
        }
        p ^= 1;
    }
}

// ---------------------------------------------------------------------
// kNN (R14 version: precomputed pn + redux-based round min).
// ---------------------------------------------------------------------
__global__ void knn_kernel(const float* __restrict__ coords,
                           const float* __restrict__ centers) {
    const int m = blockIdx.x, b = blockIdx.y, tid = threadIdx.x;
    __shared__ unsigned long long skey[N_];
    __shared__ unsigned long long scur[256];
    __shared__ unsigned long long s_win;

    const float* cx = coords + (b * 3 + 0) * N_;
    const float* cy = coords + (b * 3 + 1) * N_;
    const float* cz = coords + (b * 3 + 2) * N_;
    const float* pnb = g_pn + b * N_;
    const float qx = centers[(b * 3 + 0) * M_ + m];
    const float qy = centers[(b * 3 + 1) * M_ + m];
    const float qz = centers[(b * 3 + 2) * M_ + m];
    const float cn = fmaf(qz, qz, fmaf(qy, qy, __fmul_rn(qx, qx)));

    for (int n = tid; n < N_; n += 256) {
        float x = cx[n], y = cy[n], z = cz[n];
        float pn = pnb[n];
        float dt = fmaf(qz, z, fmaf(qy, y, __fmul_rn(qx, x)));
        float d  = __fsub_rn(__fadd_rn(cn, pn), __fmul_rn(2.0f, dt));
        unsigned ub = __float_as_uint(d);
        ub = (ub & 0x80000000u) ? ~ub : (ub | 0x80000000u);
        skey[n] = ((unsigned long long)ub << 32) | (unsigned)n;
    }
    {
        unsigned long long best = ~0ull;
#pragma unroll
        for (int j = 0; j < N_ / 256; j++) {
            unsigned long long v = skey[tid + j * 256];
            best = (v < best) ? v : best;
        }
        scur[tid] = best;
    }
    __syncthreads();

    int* outp = g_nidx + (b * M_ + m) * K_;
    for (int r = 0; r < K_; r++) {
        if (tid < 32) {
            unsigned long long mk = scur[tid];
#pragma unroll
            for (int j = 1; j < 8; j++) {
                unsigned long long v = scur[tid + j * 32];
                mk = (v < mk) ? v : mk;
            }
            unsigned hi   = (unsigned)(mk >> 32);
            unsigned hmin = __reduce_min_sync(0xffffffffu, hi);
            unsigned lo   = (hi == hmin) ? (unsigned)mk : 0xffffffffu;
            unsigned lmin = __reduce_min_sync(0xffffffffu, lo);
            if (tid == 0) {
                s_win  = ((unsigned long long)hmin << 32) | lmin;
                outp[r] = (int)lmin;
            }
        }
        __syncthreads();
        unsigned long long wk = s_win;
        if (scur[tid] == wk) {
            unsigned long long best = ~0ull;
#pragma unroll
            for (int j = 0; j < N_ / 256; j++) {
                int pos = tid + j * 256;
                unsigned long long v = skey[pos];
                if (v == wk) { skey[pos] = ~0ull; v = ~0ull; }
                best = (v < best) ? v : best;
            }
            scur[tid] = best;
        }
        __syncthreads();
    }
}

// ---------------------------------------------------------------------
// MLP1 (R13-exact body): stride-67 sF, scalar fmaf GEMM, 2-m blocking,
// fused GN1 partials, gtemb max.
// ---------------------------------------------------------------------
__global__ __launch_bounds__(256) void mlp1_kernel(
        const float* __restrict__ coords,
        const float* __restrict__ W1,
        const float* __restrict__ b1,
        const float* __restrict__ centers,
        float* __restrict__ out_temb) {
    const int b = blockIdx.y, m0 = blockIdx.x * 2, tid = threadIdx.x;
    __shared__ float sW[C1_ * 67];
    __shared__ float sF[2][K_ * 67];
    __shared__ int   sN[2][K_];

    for (int i = tid; i < C1_ * 67; i += 256) sW[i] = W1[i];
    if (tid < 64) {
        int mt = tid >> 5, kk = tid & 31;
        sN[mt][kk] = g_nidx[(b * M_ + m0 + mt) * K_ + kk];
    }
    __syncthreads();

    for (int i = tid; i < 2 * 2048; i += 256) {
        int mt = i >> 11, r = i & 2047, kk = r >> 6, c = r & 63;
        sF[mt][kk * 67 + 3 + c] = g_fT[((size_t)b * N_ + sN[mt][kk]) * 64 + c];
    }
    {
        int mt = tid >> 7, r = tid & 127, kk = r >> 2, d = r & 3;
        if (d < 3) {
            float ctr = centers[(b * 3 + d) * M_ + m0 + mt];
            sF[mt][kk * 67 + d] =
                __fsub_rn(coords[(b * 3 + d) * N_ + sN[mt][kk]], ctr);
        }
    }
    if (tid < 128) {
        int mt = tid >> 6, c = tid & 63;
        float mx = -FLT_MAX;
#pragma unroll
        for (int kk = 0; kk < K_; kk++)
            mx = fmaxf(mx, g_tT[((size_t)b * N_ + sN[mt][kk]) * 64 + c]);
        out_temb[(b * CT_ + c) * M_ + m0 + mt] = mx;
    }
    __syncthreads();

    const int k = tid & 31, og = tid >> 5, ob = og * 8;
    float a0[8], a1[8];
#pragma unroll
    for (int o = 0; o < 8; o++) { a0[o] = b1[ob + o]; a1[o] = a0[o]; }
    for (int c = 0; c < 67; c++) {
        float f0 = sF[0][k * 67 + c];
        float f1 = sF[1][k * 67 + c];
#pragma unroll
        for (int o = 0; o < 8; o++) {
            float w = sW[(ob + o) * 67 + c];
            a0[o] = fmaf(w, f0, a0[o]);
            a1[o] = fmaf(w, f1, a1[o]);
        }
    }
    double ds = 0.0, dsq = 0.0;
#pragma unroll
    for (int o = 0; o < 8; o++) {
        g_z1[((size_t)(b * C1_ + ob + o) * M_ + m0 + 0) * K_ + k] = a0[o];
        g_z1[((size_t)(b * C1_ + ob + o) * M_ + m0 + 1) * K_ + k] = a1[o];
        ds  += (double)a0[o] + (double)a1[o];
        dsq += (double)a0[o] * (double)a0[o] + (double)a1[o] * (double)a1[o];
    }
#pragma unroll
    for (int off = 16; off > 0; off >>= 1) {
        ds  += __shfl_down_sync(0xffffffffu, ds,  off);
        dsq += __shfl_down_sync(0xffffffffu, dsq, off);
    }
    if (k == 0) {
        size_t slot = ((size_t)(b * G_ + og) * 512 + blockIdx.x) * 2;
        g_p1[slot] = ds; g_p1[slot + 1] = dsq;
    }
}

// ---------------------------------------------------------------------
template <int PHASE>
__global__ void gn_fin_kernel() {
    const int    tiles = PHASE ? 256 : 512;
    const double cnt   = PHASE ? 524288.0 : 262144.0;
    const double* part = PHASE ? g_p2 : g_p1;
    float* ms          = PHASE ? g_ms2 : g_ms1;
    const int g = threadIdx.x >> 3, j = threadIdx.x & 7;
    double s = 0.0, sq = 0.0;
    for (int i = j; i < tiles; i += 8) {
        s  += part[((size_t)g * tiles + i) * 2];
        sq += part[((size_t)g * tiles + i) * 2 + 1];
    }
#pragma unroll
    for (int off = 4; off > 0; off >>= 1) {
        s  += __shfl_down_sync(0xffffffffu, s,  off);
        sq += __shfl_down_sync(0xffffffffu, sq, off);
    }
    if (j == 0) {
        double mean = s / cnt;
        double var  = sq / cnt - mean * mean;
        if (var < 0.0) var = 0.0;
        ms[g * 2]     = (float)mean;
        ms[g * 2 + 1] = (float)rsqrt(var + 1e-5);
    }
}

// ---------------------------------------------------------------------
// MLP2 (R13-exact body): sH [c][k] stride 32, scalar fmaf GEMM,
// 2-m blocking x 2 passes, fused GN2 partials.
// ---------------------------------------------------------------------
__global__ __launch_bounds__(256) void mlp2_kernel(
        const float* __restrict__ W2,
        const float* __restrict__ b2,
        const float* __restrict__ g1,
        const float* __restrict__ be1) {
    const int b = blockIdx.y, m0 = blockIdx.x * 4, tid = threadIdx.x;
    __shared__ float sW[C2_ * C1_];
    __shared__ float sH[2][C1_ * K_];
    for (int i = tid; i < C2_ * C1_; i += 256) sW[i] = W2[i];

    const int k = tid & 31, og = tid >> 5, ob = og * 16;
    double ds = 0.0, dsq = 0.0;

    for (int pr = 0; pr < 2; pr++) {
        const int m = m0 + pr * 2;
        __syncthreads();
        for (int i = tid; i < 2 * C1_ * K_; i += 256) {
            int mt = i >> 11, r = i & 2047, c = r >> 5, kk = r & 31;
            float v = g_z1[((size_t)(b * C1_ + c) * M_ + m + mt) * K_ + kk];
            int g = c >> 3;
            float mean = g_ms1[(b * G_ + g) * 2];
            float rstd = g_ms1[(b * G_ + g) * 2 + 1];
            float t = fmaf(__fmul_rn(__fsub_rn(v, mean), rstd), g1[c], be1[c]);
            float sg = 1.0f / (1.0f + expf(-t));
            sH[mt][c * K_ + kk] = t * sg;
        }
        __syncthreads();

        float a0[16], a1[16];
#pragma unroll
        for (int o = 0; o < 16; o++) { a0[o] = b2[ob + o]; a1[o] = a0[o]; }
        for (int c = 0; c < C1_; c++) {
            float f0 = sH[0][c * K_ + k];
            float f1 = sH[1][c * K_ + k];
#pragma unroll
            for (int o = 0; o < 16; o++) {
                float w = sW[(ob + o) * C1_ + c];
                a0[o] = fmaf(w, f0, a0[o]);
                a1[o] = fmaf(w, f1, a1[o]);
            }
        }
#pragma unroll
        for (int o = 0; o < 16; o++) {
            g_z2[((size_t)(b * C2_ + ob + o) * M_ + m + 0) * K_ + k] = a0[o];
            g_z2[((size_t)(b * C2_ + ob + o) * M_ + m + 1) * K_ + k] = a1[o];
            ds  += (double)a0[o] + (double)a1[o];
            dsq += (double)a0[o] * (double)a0[o] + (double)a1[o] * (double)a1[o];
        }
    }
#pragma unroll
    for (int off = 16; off > 0; off >>= 1) {
        ds  += __shfl_down_sync(0xffffffffu, ds,  off);
        dsq += __shfl_down_sync(0xffffffffu, dsq, off);
    }
    if (k == 0) {
        size_t slot = ((size_t)(b * G_ + og) * 256 + blockIdx.x) * 2;
        g_p2[slot] = ds; g_p2[slot + 1] = dsq;
    }
}

// ---------------------------------------------------------------------
__global__ void out_kernel(const float* __restrict__ g2,
                           const float* __restrict__ be2,
                           float* __restrict__ out) {
    const int idx = blockIdx.x * 256 + threadIdx.x;
    const int c = (idx >> 10) & (C2_ - 1);
    const int b = idx >> 17;
    const float mean = g_ms2[(b * G_ + (c >> 4)) * 2];
    const float rstd = g_ms2[(b * G_ + (c >> 4)) * 2 + 1];
    const float gam = g2[c], bet = be2[c];
    const float4* p = (const float4*)(g_z2 + (size_t)idx * K_);
    float mx = -FLT_MAX;
#pragma unroll
    for (int j = 0; j < K_ / 4; j++) {
        float4 v = p[j];
        float vv[4] = {v.x, v.y, v.z, v.w};
#pragma unroll
        for (int q = 0; q < 4; q++) {
            float t = fmaf(__fmul_rn(__fsub_rn(vv[q], mean), rstd), gam, bet);
            float s = t / (1.0f + expf(-t));
            mx = fmaxf(mx, s);
        }
    }
    out[idx] = mx;
}

// ---------------------------------------------------------------------
extern "C" void kernel_launch(void* const* d_in, const int* in_sizes, int n_in,
                              void* d_out, int out_size) {
    const float* features = (const float*)d_in[0];
    const float* coords   = (const float*)d_in[1];
    const float* temb     = (const float*)d_in[2];
    const float* W1  = (const float*)d_in[3];
    const float* b1  = (const float*)d_in[4];
    const float* g1  = (const float*)d_in[5];
    const float* be1 = (const float*)d_in[6];
    const float* W2  = (const float*)d_in[7];
    const float* b2  = (const float*)d_in[8];
    const float* g2  = (const float*)d_in[9];
    const float* be2 = (const float*)d_in[10];

    float* out      = (float*)d_out;
    float* out_h    = out;                    // [B, C2, M]
    float* out_ctr  = out + B_ * C2_ * M_;    // [B, 3, M]
    float* out_temb = out_ctr + B_ * 3 * M_;  // [B, CT, M]

    fps_kernel<<<B_, 256>>>(coords, out_ctr);                       // idx 0
    pn_kernel<<<(B_ * N_) / 256, 256>>>(coords);                    // idx 1
    tr_kernel<0><<<dim3(N_ / 32, 2, B_), dim3(32, 32)>>>(features); // idx 2
    knn_kernel<<<dim3(M_, B_), 256>>>(coords, out_ctr);             // idx 3 (profiled)
    tr_kernel<1><<<dim3(N_ / 32, 2, B_), dim3(32, 32)>>>(temb);     // idx 4
    mlp1_kernel<<<dim3(M_ / 2, B_), 256>>>(coords, W1, b1, out_ctr, out_temb);
    gn_fin_kernel<0><<<1, 512>>>();
    mlp2_kernel<<<dim3(M_ / 4, B_), 256>>>(W2, b2, g1, be1);
    gn_fin_kernel<1><<<1, 512>>>();
    out_kernel<<<(B_ * C2_ * M_) / 256, 256>>>(g2, be2, out_h);
}